// round 10
// baseline (speedup 1.0000x reference)
#include <cuda_runtime.h>
#include <math.h>
#include <stdint.h>

#define NB   32
#define CD   512
#define TD   2048
#define NT   (NB * TD)        // 65536
#define KCODE 512
#define QL   6
#define NCT  (NB * CD * TD)   // 33554432

#define IDX_OFF   ((size_t)NCT)
#define LOSS_OFF  (IDX_OFF + (size_t)NT * QL)   // 33947648
#define OUT_TOTAL (LOSS_OFF + 2)                 // 33947650

#define FULLM 0xffffffffu

// ---------------- device scratch (static globals; no runtime alloc) -------
__device__ float g_res[(size_t)NT * CD];   // residual state, row-major [(n,t), c]
__device__ float g_cc[QL * KCODE];         // ||c||^2, serial ascending schedule
__device__ int   g_code[QL * NT];
__device__ float g_hist[QL * KCODE];
__device__ float g_losspart[QL * 1024];

// ---------------- prep: zero hist + code norms ----------------------------
// XLA:CPU non-vectorized reduce: strictly serial ascending, separate mul/add.
__global__ void prep_kernel(const float* __restrict__ cb)
{
    int gid = blockIdx.x * 256 + threadIdx.x;
    if (gid < QL * KCODE) {
        g_hist[gid] = 0.0f;
        const float* row = cb + (size_t)gid * CD;
        float a = 0.0f;
        #pragma unroll 8
        for (int k = 0; k < CD; k++) {
            float v = row[k];
            a = __fadd_rn(a, __fmul_rn(v, v));
        }
        g_cc[gid] = a;
    }
}

// ---------------- transpose x [N,C,T] -> residual [(n,t), c] --------------
__global__ void transpose_in_kernel(const float* __restrict__ x)
{
    __shared__ float s[32][33];
    int n = blockIdx.z, c0 = blockIdx.y * 32, t0 = blockIdx.x * 32;
    int tx = threadIdx.x, ty = threadIdx.y;
    #pragma unroll
    for (int i = 0; i < 4; i++) {
        int cc = ty + 8 * i;
        s[cc][tx] = x[(size_t)n * CD * TD + (size_t)(c0 + cc) * TD + t0 + tx];
    }
    __syncthreads();
    #pragma unroll
    for (int i = 0; i < 4; i++) {
        int tt = ty + 8 * i;
        g_res[(size_t)(n * TD + t0 + tt) * CD + c0 + tx] = s[tx][tt];
    }
}

// ---------------- fused VQ layer: scores + argmin + update ----------------
// 512 threads, 64 rows x 512 codes per block; warp w owns rows 4w..4w+3.
// Per-lane code pattern 2l+64i (identical numerics to the passing R8 kernel).
#define SA_STRIDE 66
#define SA_WORDS  (512 * SA_STRIDE)
#define SB_WORDS  (8 * 512)
#define SMEM_FLOATS (SA_WORDS + 2 * SB_WORDS + 512 + 32)
#define SMEM_BYTES (SMEM_FLOATS * 4)

__global__ __launch_bounds__(512, 1) void vq_layer_kernel(const float* __restrict__ cb_all, int q)
{
    extern __shared__ float sm[];
    float* sA  = sm;
    float* sB  = sm + SA_WORDS;
    float* sCc = sm + SA_WORDS + 2 * SB_WORDS;
    float* sSt = sCc + 512;

    const float* cbq = cb_all + (size_t)q * KCODE * CD;
    const int t = threadIdx.x;
    const int bid = blockIdx.x;
    const int r0 = bid * 64;

    if (t < 512) sCc[t] = g_cc[q * 512 + t];

    // stage A (64 rows x 512) into [k][row] layout
    const float* resblk = g_res + (size_t)r0 * CD;
    #pragma unroll 4
    for (int j = 0; j < 64; j++) {
        int e = t + 512 * j;
        int row = e >> 9;
        int k = e & 511;
        sA[k * SA_STRIDE + row] = resblk[e];
    }

    // stage first B chunk: thread t loads code t, 8 k values
    float4 p0, p1;
    {
        const float* b0 = cbq + (size_t)t * CD;
        p0 = *(const float4*)b0;
        p1 = *(const float4*)(b0 + 4);
    }
    {
        float* d = sB;
        d[0*512 + t] = p0.x; d[1*512 + t] = p0.y; d[2*512 + t] = p0.z; d[3*512 + t] = p0.w;
        d[4*512 + t] = p1.x; d[5*512 + t] = p1.y; d[6*512 + t] = p1.z; d[7*512 + t] = p1.w;
    }
    __syncthreads();

    unsigned long long acc[4][8];
    #pragma unroll
    for (int rr = 0; rr < 4; rr++)
        #pragma unroll
        for (int i = 0; i < 8; i++) acc[rr][i] = 0ull;

    const int w = t >> 5, l = t & 31;
    const int arow = 4 * w;

    // k strictly ascending, single fp32 accumulator per output, FMA
    #pragma unroll 1
    for (int kc = 0; kc < 512; kc += 8) {
        const int buf = (kc >> 3) & 1;
        const float* sBc = sB + buf * SB_WORDS;
        const bool more = (kc + 8) < 512;
        if (more) {
            const float* b0 = cbq + (size_t)t * CD + kc + 8;
            p0 = *(const float4*)b0;
            p1 = *(const float4*)(b0 + 4);
        }
        #pragma unroll
        for (int kk = 0; kk < 8; kk++) {
            unsigned long long b2[8];
            #pragma unroll
            for (int i = 0; i < 8; i++)
                b2[i] = *(const unsigned long long*)(sBc + kk * 512 + 2 * l + 64 * i);
            #pragma unroll
            for (int rr = 0; rr < 4; rr++) {
                float av = sA[(kc + kk) * SA_STRIDE + arow + rr];
                unsigned au = __float_as_uint(av);
                unsigned long long a2;
                asm("mov.b64 %0, {%1, %1};" : "=l"(a2) : "r"(au));
                #pragma unroll
                for (int i = 0; i < 8; i++)
                    asm("fma.rn.f32x2 %0, %1, %2, %0;"
                        : "+l"(acc[rr][i]) : "l"(a2), "l"(b2[i]));
            }
        }
        if (more) {
            float* d = sB + (buf ^ 1) * SB_WORDS;
            d[0*512 + t] = p0.x; d[1*512 + t] = p0.y; d[2*512 + t] = p0.z; d[3*512 + t] = p0.w;
            d[4*512 + t] = p1.x; d[5*512 + t] = p1.y; d[6*512 + t] = p1.z; d[7*512 + t] = p1.w;
        }
        __syncthreads();
    }

    // ---- xx per row: strictly serial ascending scalar (XLA:CPU schedule) ----
    // lanes 0..3 each own one of this warp's 4 rows; single accumulator,
    // separate mul/add, k = 0..511 ascending.
    float xxser = 0.0f;
    if (l < 4) {
        const int row = arow + l;
        float a = 0.0f;
        #pragma unroll 8
        for (int k = 0; k < 512; k++) {
            float v = sA[k * SA_STRIDE + row];
            a = __fadd_rn(a, __fmul_rn(v, v));
        }
        xxser = a;
    }

    // epilogue: dist = (xx - 2*dot) + cc, argmin (min-index ties), ST update
    float warploss = 0.0f;
    #pragma unroll 1
    for (int rr = 0; rr < 4; rr++) {
        const int row = arow + rr;
        const float xx = __shfl_sync(FULLM, xxser, rr);

        float best = 3.4e38f; int bidx = 0;
        #pragma unroll
        for (int i = 0; i < 8; i++) {
            unsigned long long v = acc[rr][i];
            float d0 = __uint_as_float((unsigned)(v & 0xffffffffull));
            float d1 = __uint_as_float((unsigned)(v >> 32));
            int c0 = 2 * l + 64 * i;
            float dist0 = __fadd_rn(__fsub_rn(xx, __fmul_rn(2.0f, d0)), sCc[c0]);
            float dist1 = __fadd_rn(__fsub_rn(xx, __fmul_rn(2.0f, d1)), sCc[c0 + 1]);
            if (dist0 < best) { best = dist0; bidx = c0; }
            if (dist1 < best) { best = dist1; bidx = c0 + 1; }
        }
        #pragma unroll
        for (int o = 16; o; o >>= 1) {
            float ob = __shfl_xor_sync(FULLM, best, o);
            int   oi = __shfl_xor_sync(FULLM, bidx, o);
            if (ob < best || (ob == best && oi < bidx)) { best = ob; bidx = oi; }
        }

        // straight-through residual update replicated op-for-op + commit loss
        const float* crow = cbq + (size_t)bidx * CD;
        float* rrow = g_res + (size_t)(r0 + row) * CD;
        #pragma unroll
        for (int j = 0; j < 16; j++) {
            int k = l + 32 * j;
            float r = sA[k * SA_STRIDE + row];
            float c = crow[k];
            float xst  = __fadd_rn(r, __fsub_rn(c, r));   // xf + (x_d - xf)
            rrow[k]    = __fsub_rn(r, xst);               // residual - quantized
            float diff = __fsub_rn(r, c);                 // xf - x_d
            warploss += diff * diff;                      // scalar; loose tolerance
        }
        if (l == 0) {
            g_code[q * NT + r0 + row] = bidx;
            atomicAdd(&g_hist[q * 512 + bidx], 1.0f);
        }
    }
    #pragma unroll
    for (int o = 16; o; o >>= 1) warploss += __shfl_xor_sync(FULLM, warploss, o);
    if (l == 0) sSt[w] = warploss;
    __syncthreads();
    if (t == 0) {
        float s = 0.0f;
        #pragma unroll
        for (int i = 0; i < 16; i++) s += sSt[i];
        g_losspart[q * 1024 + bid] = s;
    }
}

// ---------------- output: quantized = x - residual_final (transposed) -----
__global__ void write_quant_kernel(const float* __restrict__ x, float* __restrict__ out)
{
    __shared__ float s[32][33];
    int n = blockIdx.z, c0 = blockIdx.y * 32, t0 = blockIdx.x * 32;
    int tx = threadIdx.x, ty = threadIdx.y;
    #pragma unroll
    for (int i = 0; i < 4; i++) {
        int tt = ty + 8 * i;
        s[tt][tx] = g_res[(size_t)(n * TD + t0 + tt) * CD + c0 + tx];
    }
    __syncthreads();
    #pragma unroll
    for (int i = 0; i < 4; i++) {
        int cc = ty + 8 * i;
        size_t o = (size_t)n * CD * TD + (size_t)(c0 + cc) * TD + t0 + tx;
        out[o] = __fsub_rn(x[o], s[tx][cc]);
    }
}

__global__ void write_idx_kernel(float* __restrict__ out, int out_size)
{
    int nt = blockIdx.x * 256 + threadIdx.x;
    if (nt < NT && (size_t)out_size >= OUT_TOTAL) {
        #pragma unroll
        for (int q = 0; q < QL; q++)
            out[IDX_OFF + (size_t)nt * QL + q] = (float)g_code[q * NT + nt];
    }
}

__global__ void finalize_kernel(float* __restrict__ out, int out_size)
{
    __shared__ float red[512];
    const int t = threadIdx.x;
    float tot_loss = 0.0f, tot_perp = 0.0f;
    for (int q = 0; q < QL; q++) {
        red[t] = g_losspart[q * 1024 + t] + g_losspart[q * 1024 + 512 + t];
        __syncthreads();
        for (int st = 256; st > 0; st >>= 1) {
            if (t < st) red[t] += red[t + st];
            __syncthreads();
        }
        tot_loss += red[0];
        __syncthreads();

        float p = g_hist[q * 512 + t] * (1.0f / 65536.0f);
        red[t] = p * logf(p + 1e-7f);
        __syncthreads();
        for (int st = 256; st > 0; st >>= 1) {
            if (t < st) red[t] += red[t + st];
            __syncthreads();
        }
        tot_perp += expf(-red[0]);
        __syncthreads();
    }
    if (t == 0 && (size_t)out_size >= OUT_TOTAL) {
        out[LOSS_OFF]     = tot_loss * (1.0f / ((float)NT * (float)CD)) / (float)QL;
        out[LOSS_OFF + 1] = tot_perp / (float)QL;
    }
}

// ---------------- launch --------------------------------------------------
extern "C" void kernel_launch(void* const* d_in, const int* in_sizes, int n_in,
                              void* d_out, int out_size)
{
    const float* x  = (const float*)d_in[0];
    const float* cb = (const float*)d_in[1];
    if (n_in >= 2 && in_sizes[0] < in_sizes[1]) {
        const float* tmp = x; x = cb; cb = tmp;
    }
    float* out = (float*)d_out;

    cudaFuncSetAttribute(vq_layer_kernel,
                         cudaFuncAttributeMaxDynamicSharedMemorySize, SMEM_BYTES);

    prep_kernel<<<12, 256>>>(cb);
    transpose_in_kernel<<<dim3(TD / 32, CD / 32, NB), dim3(32, 8)>>>(x);
    for (int q = 0; q < QL; q++)
        vq_layer_kernel<<<NT / 64, 512, SMEM_BYTES>>>(cb, q);
    write_quant_kernel<<<dim3(TD / 32, CD / 32, NB), dim3(32, 8)>>>(x, out);
    write_idx_kernel<<<NT / 256, 256>>>(out, out_size);
    finalize_kernel<<<1, 512>>>(out, out_size);
}

// round 13
// speedup vs baseline: 1.1111x; 1.1111x over previous
#include <cuda_runtime.h>
#include <math.h>
#include <stdint.h>

#define NB   32
#define CD   512
#define TD   2048
#define NT   (NB * TD)        // 65536
#define KCODE 512
#define QL   6
#define NCT  (NB * CD * TD)   // 33554432

#define IDX_OFF   ((size_t)NCT)
#define LOSS_OFF  (IDX_OFF + (size_t)NT * QL)   // 33947648
#define OUT_TOTAL (LOSS_OFF + 2)                 // 33947650

#define FULLM 0xffffffffu

// ---------------- device scratch (static globals; no runtime alloc) -------
__device__ float g_res[(size_t)NT * CD];   // residual state, row-major [(n,t), c]
__device__ float g_cbT[QL * KCODE * CD];   // codebook transposed: [q][k][code]
__device__ float g_cc[QL * KCODE];         // ||c||^2, serial ascending schedule
__device__ int   g_code[QL * NT];
__device__ float g_hist[QL * KCODE];
__device__ float g_losspart[QL * 1024];

// ---------------- prep: zero hist + code norms ----------------------------
// XLA:CPU non-vectorized reduce: strictly serial ascending, separate mul/add.
__global__ void prep_kernel(const float* __restrict__ cb)
{
    int gid = blockIdx.x * 256 + threadIdx.x;
    if (gid < QL * KCODE) {
        g_hist[gid] = 0.0f;
        const float* row = cb + (size_t)gid * CD;
        float a = 0.0f;
        #pragma unroll 8
        for (int k = 0; k < CD; k++) {
            float v = row[k];
            a = __fadd_rn(a, __fmul_rn(v, v));
        }
        g_cc[gid] = a;
    }
}

// ---------------- transpose codebook: [q][code][k] -> [q][k][code] --------
__global__ void transpose_cb_kernel(const float* __restrict__ cb)
{
    __shared__ float s[32][33];
    int qq = blockIdx.z, c0 = blockIdx.x * 32, k0 = blockIdx.y * 32;
    int tx = threadIdx.x, ty = threadIdx.y;
    const float* src = cb + (size_t)qq * KCODE * CD;
    float* dst = g_cbT + (size_t)qq * KCODE * CD;
    #pragma unroll
    for (int i = 0; i < 4; i++) {
        int cc = ty + 8 * i;
        s[cc][tx] = src[(size_t)(c0 + cc) * CD + k0 + tx];
    }
    __syncthreads();
    #pragma unroll
    for (int i = 0; i < 4; i++) {
        int kk = ty + 8 * i;
        dst[(size_t)(k0 + kk) * KCODE + c0 + tx] = s[tx][kk];
    }
}

// ---------------- transpose x [N,C,T] -> residual [(n,t), c] --------------
__global__ void transpose_in_kernel(const float* __restrict__ x)
{
    __shared__ float s[32][33];
    int n = blockIdx.z, c0 = blockIdx.y * 32, t0 = blockIdx.x * 32;
    int tx = threadIdx.x, ty = threadIdx.y;
    #pragma unroll
    for (int i = 0; i < 4; i++) {
        int cc = ty + 8 * i;
        s[cc][tx] = x[(size_t)n * CD * TD + (size_t)(c0 + cc) * TD + t0 + tx];
    }
    __syncthreads();
    #pragma unroll
    for (int i = 0; i < 4; i++) {
        int tt = ty + 8 * i;
        g_res[(size_t)(n * TD + t0 + tt) * CD + c0 + tx] = s[tx][tt];
    }
}

// ---------------- cp.async helpers ----------------------------------------
__device__ __forceinline__ void cp_async16(uint32_t smem_addr, const void* gptr)
{
    asm volatile("cp.async.cg.shared.global [%0], [%1], 16;\n"
                 :: "r"(smem_addr), "l"(gptr) : "memory");
}
__device__ __forceinline__ void cp_commit() {
    asm volatile("cp.async.commit_group;\n" ::: "memory");
}
__device__ __forceinline__ void cp_wait2() {
    asm volatile("cp.async.wait_group 2;\n" ::: "memory");
}

// ---------------- fused VQ layer: scores + argmin + update ----------------
// 256 threads, 64 rows x 512 codes per block; warp w owns rows 8w..8w+7.
// B staged from g_cbT via 4-stage cp.async ring (chunk = 8 k x 512 codes).
#define SA_STRIDE 66
#define SA_WORDS  (512 * SA_STRIDE)      // 33792 floats
#define SB_STAGE  (8 * 512)              // 4096 floats per stage
#define NSTAGE    4
#define SMEM_FLOATS (SA_WORDS + NSTAGE * SB_STAGE + 512 + 16)
#define SMEM_BYTES (SMEM_FLOATS * 4)     // 202816 B

__global__ __launch_bounds__(256, 1) void vq_layer_kernel(const float* __restrict__ cb_all, int q)
{
    extern __shared__ float sm[];
    float* sA  = sm;
    float* sB  = sm + SA_WORDS;
    float* sCc = sm + SA_WORDS + NSTAGE * SB_STAGE;
    float* sSt = sCc + 512;

    const float* cbq  = cb_all + (size_t)q * KCODE * CD;   // row-major (epilogue)
    const float* cbTq = g_cbT + (size_t)q * KCODE * CD;    // [k][code] (mainloop)
    const int t = threadIdx.x;
    const int bid = blockIdx.x;
    const int r0 = bid * 64;

    const uint32_t sB_u32 = (uint32_t)__cvta_generic_to_shared(sB);

    for (int i = t; i < 512; i += 256) sCc[i] = g_cc[q * 512 + i];

    // prologue: issue cp.async for stages 0..2 (chunk = 16KB, 64B/thread)
    #pragma unroll
    for (int s = 0; s < 3; s++) {
        uint32_t dst = sB_u32 + (uint32_t)(s * SB_STAGE + t * 16) * 4;
        const float* src = cbTq + (size_t)s * SB_STAGE + t * 16;
        cp_async16(dst,      src);
        cp_async16(dst + 16, src + 4);
        cp_async16(dst + 32, src + 8);
        cp_async16(dst + 48, src + 12);
        cp_commit();
    }

    // stage A (64 rows x 512) into [k][row] layout
    const float* resblk = g_res + (size_t)r0 * CD;
    #pragma unroll 4
    for (int j = 0; j < 128; j++) {
        int e = t + 256 * j;
        int row = e >> 9;
        int k = e & 511;
        sA[k * SA_STRIDE + row] = resblk[e];
    }

    unsigned long long acc[8][8];
    #pragma unroll
    for (int rr = 0; rr < 8; rr++)
        #pragma unroll
        for (int i = 0; i < 8; i++) acc[rr][i] = 0ull;

    const int w = t >> 5, l = t & 31;
    const int arow = 8 * w;

    // k strictly ascending, single fp32 accumulator per output, FMA
    // (bit-identical chains to the passing R8 kernel)
    #pragma unroll 1
    for (int s = 0; s < 64; s++) {
        const int kc = 8 * s;
        cp_wait2();              // group s complete (this thread's copies)
        __syncthreads();         // all threads' copies visible; prev stage consumed

        // issue stage s+3 (buffer (s+3)&3 was consumed at iter s-1)
        if (s + 3 < 64) {
            uint32_t dst = sB_u32 + (uint32_t)(((s + 3) & 3) * SB_STAGE + t * 16) * 4;
            const float* src = cbTq + (size_t)(s + 3) * SB_STAGE + t * 16;
            cp_async16(dst,      src);
            cp_async16(dst + 16, src + 4);
            cp_async16(dst + 32, src + 8);
            cp_async16(dst + 48, src + 12);
        }
        cp_commit();             // always commit (empty groups keep wait_group exact)

        const float* sBc = sB + (s & 3) * SB_STAGE;
        #pragma unroll
        for (int kk = 0; kk < 8; kk++) {
            unsigned long long b2[8];
            #pragma unroll
            for (int i = 0; i < 8; i++)
                b2[i] = *(const unsigned long long*)(sBc + kk * 512 + 2 * l + 64 * i);
            #pragma unroll
            for (int rr = 0; rr < 8; rr++) {
                float av = sA[(kc + kk) * SA_STRIDE + arow + rr];
                unsigned au = __float_as_uint(av);
                unsigned long long a2;
                asm("mov.b64 %0, {%1, %1};" : "=l"(a2) : "r"(au));
                #pragma unroll
                for (int i = 0; i < 8; i++)
                    asm("fma.rn.f32x2 %0, %1, %2, %0;"
                        : "+l"(acc[rr][i]) : "l"(a2), "l"(b2[i]));
            }
        }
    }

    // ---- xx per row: strictly serial ascending scalar (XLA:CPU schedule) ----
    float xxser = 0.0f;
    if (l < 8) {
        const int row = arow + l;
        float a = 0.0f;
        #pragma unroll 8
        for (int k = 0; k < 512; k++) {
            float v = sA[k * SA_STRIDE + row];
            a = __fadd_rn(a, __fmul_rn(v, v));
        }
        xxser = a;
    }

    // epilogue: dist = (xx - 2*dot) + cc, argmin (min-index ties), ST update
    float warploss = 0.0f;
    #pragma unroll 1
    for (int rr = 0; rr < 8; rr++) {
        const int row = arow + rr;
        const float xx = __shfl_sync(FULLM, xxser, rr);

        float best = 3.4e38f; int bidx = 0;
        #pragma unroll
        for (int i = 0; i < 8; i++) {
            unsigned long long v = acc[rr][i];
            float d0 = __uint_as_float((unsigned)(v & 0xffffffffull));
            float d1 = __uint_as_float((unsigned)(v >> 32));
            int c0 = 2 * l + 64 * i;
            float dist0 = __fadd_rn(__fsub_rn(xx, __fmul_rn(2.0f, d0)), sCc[c0]);
            float dist1 = __fadd_rn(__fsub_rn(xx, __fmul_rn(2.0f, d1)), sCc[c0 + 1]);
            if (dist0 < best) { best = dist0; bidx = c0; }
            if (dist1 < best) { best = dist1; bidx = c0 + 1; }
        }
        #pragma unroll
        for (int o = 16; o; o >>= 1) {
            float ob = __shfl_xor_sync(FULLM, best, o);
            int   oi = __shfl_xor_sync(FULLM, bidx, o);
            if (ob < best || (ob == best && oi < bidx)) { best = ob; bidx = oi; }
        }

        // straight-through residual update replicated op-for-op + commit loss
        const float* crow = cbq + (size_t)bidx * CD;
        float* rrow = g_res + (size_t)(r0 + row) * CD;
        #pragma unroll
        for (int j = 0; j < 16; j++) {
            int k = l + 32 * j;
            float r = sA[k * SA_STRIDE + row];
            float c = crow[k];
            float xst  = __fadd_rn(r, __fsub_rn(c, r));   // xf + (x_d - xf)
            rrow[k]    = __fsub_rn(r, xst);               // residual - quantized
            float diff = __fsub_rn(r, c);                 // xf - x_d
            warploss += diff * diff;                      // scalar; loose tolerance
        }
        if (l == 0) {
            g_code[q * NT + r0 + row] = bidx;
            atomicAdd(&g_hist[q * 512 + bidx], 1.0f);
        }
    }
    #pragma unroll
    for (int o = 16; o; o >>= 1) warploss += __shfl_xor_sync(FULLM, warploss, o);
    if (l == 0) sSt[w] = warploss;
    __syncthreads();
    if (t == 0) {
        float s = 0.0f;
        #pragma unroll
        for (int i = 0; i < 8; i++) s += sSt[i];
        g_losspart[q * 1024 + bid] = s;
    }
}

// ---------------- output: quantized = x - residual_final (transposed) -----
__global__ void write_quant_kernel(const float* __restrict__ x, float* __restrict__ out)
{
    __shared__ float s[32][33];
    int n = blockIdx.z, c0 = blockIdx.y * 32, t0 = blockIdx.x * 32;
    int tx = threadIdx.x, ty = threadIdx.y;
    #pragma unroll
    for (int i = 0; i < 4; i++) {
        int tt = ty + 8 * i;
        s[tt][tx] = g_res[(size_t)(n * TD + t0 + tt) * CD + c0 + tx];
    }
    __syncthreads();
    #pragma unroll
    for (int i = 0; i < 4; i++) {
        int cc = ty + 8 * i;
        size_t o = (size_t)n * CD * TD + (size_t)(c0 + cc) * TD + t0 + tx;
        out[o] = __fsub_rn(x[o], s[tx][cc]);
    }
}

__global__ void write_idx_kernel(float* __restrict__ out, int out_size)
{
    int nt = blockIdx.x * 256 + threadIdx.x;
    if (nt < NT && (size_t)out_size >= OUT_TOTAL) {
        #pragma unroll
        for (int q = 0; q < QL; q++)
            out[IDX_OFF + (size_t)nt * QL + q] = (float)g_code[q * NT + nt];
    }
}

__global__ void finalize_kernel(float* __restrict__ out, int out_size)
{
    __shared__ float red[512];
    const int t = threadIdx.x;
    float tot_loss = 0.0f, tot_perp = 0.0f;
    for (int q = 0; q < QL; q++) {
        red[t] = g_losspart[q * 1024 + t] + g_losspart[q * 1024 + 512 + t];
        __syncthreads();
        for (int st = 256; st > 0; st >>= 1) {
            if (t < st) red[t] += red[t + st];
            __syncthreads();
        }
        tot_loss += red[0];
        __syncthreads();

        float p = g_hist[q * 512 + t] * (1.0f / 65536.0f);
        red[t] = p * logf(p + 1e-7f);
        __syncthreads();
        for (int st = 256; st > 0; st >>= 1) {
            if (t < st) red[t] += red[t + st];
            __syncthreads();
        }
        tot_perp += expf(-red[0]);
        __syncthreads();
    }
    if (t == 0 && (size_t)out_size >= OUT_TOTAL) {
        out[LOSS_OFF]     = tot_loss * (1.0f / ((float)NT * (float)CD)) / (float)QL;
        out[LOSS_OFF + 1] = tot_perp / (float)QL;
    }
}

// ---------------- launch --------------------------------------------------
extern "C" void kernel_launch(void* const* d_in, const int* in_sizes, int n_in,
                              void* d_out, int out_size)
{
    const float* x  = (const float*)d_in[0];
    const float* cb = (const float*)d_in[1];
    if (n_in >= 2 && in_sizes[0] < in_sizes[1]) {
        const float* tmp = x; x = cb; cb = tmp;
    }
    float* out = (float*)d_out;

    cudaFuncSetAttribute(vq_layer_kernel,
                         cudaFuncAttributeMaxDynamicSharedMemorySize, SMEM_BYTES);

    prep_kernel<<<12, 256>>>(cb);
    transpose_cb_kernel<<<dim3(KCODE / 32, CD / 32, QL), dim3(32, 8)>>>(cb);
    transpose_in_kernel<<<dim3(TD / 32, CD / 32, NB), dim3(32, 8)>>>(x);
    for (int q = 0; q < QL; q++)
        vq_layer_kernel<<<NT / 64, 256, SMEM_BYTES>>>(cb, q);
    write_quant_kernel<<<dim3(TD / 32, CD / 32, NB), dim3(32, 8)>>>(x, out);
    write_idx_kernel<<<NT / 256, 256>>>(out, out_size);
    finalize_kernel<<<1, 512>>>(out, out_size);
}

// round 15
// speedup vs baseline: 1.1182x; 1.0063x over previous
#include <cuda_runtime.h>
#include <math.h>
#include <stdint.h>

#define NB   32
#define CD   512
#define TD   2048
#define NT   (NB * TD)        // 65536
#define KCODE 512
#define QL   6
#define NCT  (NB * CD * TD)   // 33554432

#define IDX_OFF   ((size_t)NCT)
#define LOSS_OFF  (IDX_OFF + (size_t)NT * QL)   // 33947648
#define OUT_TOTAL (LOSS_OFF + 2)                 // 33947650

#define FULLM 0xffffffffu

// ---------------- device scratch (static globals; no runtime alloc) -------
__device__ float g_res[(size_t)NT * CD];   // residual state, row-major [(n,t), c]
__device__ float g_cbT[QL * KCODE * CD];   // codebook transposed: [q][k][code]
__device__ float g_cc[QL * KCODE];         // ||c||^2, serial ascending schedule
__device__ int   g_code[QL * NT];
__device__ float g_hist[QL * KCODE];
__device__ float g_losspart[QL * 1024];

// ---------------- prep: zero hist + code norms ----------------------------
// XLA:CPU non-vectorized reduce: strictly serial ascending, separate mul/add.
__global__ void prep_kernel(const float* __restrict__ cb)
{
    int gid = blockIdx.x * 256 + threadIdx.x;
    if (gid < QL * KCODE) {
        g_hist[gid] = 0.0f;
        const float* row = cb + (size_t)gid * CD;
        float a = 0.0f;
        #pragma unroll 8
        for (int k = 0; k < CD; k++) {
            float v = row[k];
            a = __fadd_rn(a, __fmul_rn(v, v));
        }
        g_cc[gid] = a;
    }
}

// ---------------- transpose codebook: [q][code][k] -> [q][k][code] --------
__global__ void transpose_cb_kernel(const float* __restrict__ cb)
{
    __shared__ float s[32][33];
    int qq = blockIdx.z, c0 = blockIdx.x * 32, k0 = blockIdx.y * 32;
    int tx = threadIdx.x, ty = threadIdx.y;
    const float* src = cb + (size_t)qq * KCODE * CD;
    float* dst = g_cbT + (size_t)qq * KCODE * CD;
    #pragma unroll
    for (int i = 0; i < 4; i++) {
        int cc = ty + 8 * i;
        s[cc][tx] = src[(size_t)(c0 + cc) * CD + k0 + tx];
    }
    __syncthreads();
    #pragma unroll
    for (int i = 0; i < 4; i++) {
        int kk = ty + 8 * i;
        dst[(size_t)(k0 + kk) * KCODE + c0 + tx] = s[tx][kk];
    }
}

// ---------------- transpose x [N,C,T] -> residual [(n,t), c] --------------
__global__ void transpose_in_kernel(const float* __restrict__ x)
{
    __shared__ float s[32][33];
    int n = blockIdx.z, c0 = blockIdx.y * 32, t0 = blockIdx.x * 32;
    int tx = threadIdx.x, ty = threadIdx.y;
    #pragma unroll
    for (int i = 0; i < 4; i++) {
        int cc = ty + 8 * i;
        s[cc][tx] = x[(size_t)n * CD * TD + (size_t)(c0 + cc) * TD + t0 + tx];
    }
    __syncthreads();
    #pragma unroll
    for (int i = 0; i < 4; i++) {
        int tt = ty + 8 * i;
        g_res[(size_t)(n * TD + t0 + tt) * CD + c0 + tx] = s[tx][tt];
    }
}

// ---------------- cp.async helpers ----------------------------------------
__device__ __forceinline__ void cp_async16(uint32_t smem_addr, const void* gptr)
{
    asm volatile("cp.async.cg.shared.global [%0], [%1], 16;\n"
                 :: "r"(smem_addr), "l"(gptr) : "memory");
}
__device__ __forceinline__ void cp_commit() {
    asm volatile("cp.async.commit_group;\n" ::: "memory");
}
__device__ __forceinline__ void cp_wait2() {
    asm volatile("cp.async.wait_group 2;\n" ::: "memory");
}

// ---------------- fused VQ layer: scores + argmin + update ----------------
// 256 threads, 64 rows x 512 codes per block; warp w owns rows 8w..8w+7.
// B staged from g_cbT via 4-stage cp.async ring (chunk = 8 k x 512 codes).
// Inner loop software-pipelined in registers: loads for kk+1 issued before
// the 64 independent FFMA2s of kk (load->use distance >= one FFMA block).
#define SA_STRIDE 66
#define SA_WORDS  (512 * SA_STRIDE)      // 33792 floats
#define SB_STAGE  (8 * 512)              // 4096 floats per stage
#define NSTAGE    4
#define SMEM_FLOATS (SA_WORDS + NSTAGE * SB_STAGE + 512 + 16)
#define SMEM_BYTES (SMEM_FLOATS * 4)     // 202816 B

__global__ __launch_bounds__(256, 1) void vq_layer_kernel(const float* __restrict__ cb_all, int q)
{
    extern __shared__ float sm[];
    float* sA  = sm;
    float* sB  = sm + SA_WORDS;
    float* sCc = sm + SA_WORDS + NSTAGE * SB_STAGE;
    float* sSt = sCc + 512;

    const float* cbq  = cb_all + (size_t)q * KCODE * CD;   // row-major (epilogue)
    const float* cbTq = g_cbT + (size_t)q * KCODE * CD;    // [k][code] (mainloop)
    const int t = threadIdx.x;
    const int bid = blockIdx.x;
    const int r0 = bid * 64;

    const uint32_t sB_u32 = (uint32_t)__cvta_generic_to_shared(sB);

    for (int i = t; i < 512; i += 256) sCc[i] = g_cc[q * 512 + i];

    // prologue: issue cp.async for stages 0..2 (chunk = 16KB, 64B/thread)
    #pragma unroll
    for (int s = 0; s < 3; s++) {
        uint32_t dst = sB_u32 + (uint32_t)(s * SB_STAGE + t * 16) * 4;
        const float* src = cbTq + (size_t)s * SB_STAGE + t * 16;
        cp_async16(dst,      src);
        cp_async16(dst + 16, src + 4);
        cp_async16(dst + 32, src + 8);
        cp_async16(dst + 48, src + 12);
        cp_commit();
    }

    // stage A (64 rows x 512) into [k][row] layout
    const float* resblk = g_res + (size_t)r0 * CD;
    #pragma unroll 4
    for (int j = 0; j < 128; j++) {
        int e = t + 256 * j;
        int row = e >> 9;
        int k = e & 511;
        sA[k * SA_STRIDE + row] = resblk[e];
    }

    unsigned long long acc[8][8];
    #pragma unroll
    for (int rr = 0; rr < 8; rr++)
        #pragma unroll
        for (int i = 0; i < 8; i++) acc[rr][i] = 0ull;

    const int w = t >> 5, l = t & 31;
    const int arow = 8 * w;

    // double-buffered operand registers (named, distinct)
    unsigned long long b2a[8], b2b[8], a2a[8], a2b[8];

    // k strictly ascending, single fp32 accumulator per output, FMA
    // (bit-identical chains to the passing R8/R13 kernels)
    #pragma unroll 1
    for (int s = 0; s < 64; s++) {
        const int kc = 8 * s;
        cp_wait2();              // group s complete (this thread's copies)
        __syncthreads();         // all threads' copies visible; prev stage consumed

        // issue stage s+3 (buffer (s+3)&3 was consumed at iter s-1)
        if (s + 3 < 64) {
            uint32_t dst = sB_u32 + (uint32_t)(((s + 3) & 3) * SB_STAGE + t * 16) * 4;
            const float* src = cbTq + (size_t)(s + 3) * SB_STAGE + t * 16;
            cp_async16(dst,      src);
            cp_async16(dst + 16, src + 4);
            cp_async16(dst + 32, src + 8);
            cp_async16(dst + 48, src + 12);
        }
        cp_commit();             // always commit (empty groups keep wait_group exact)

        const float* sBc = sB + (s & 3) * SB_STAGE;

        // preload kk=0 operands into buffer A
        #pragma unroll
        for (int i = 0; i < 8; i++)
            b2a[i] = *(const unsigned long long*)(sBc + 0 * 512 + 2 * l + 64 * i);
        #pragma unroll
        for (int rr = 0; rr < 8; rr++) {
            unsigned au = __float_as_uint(sA[(kc + 0) * SA_STRIDE + arow + rr]);
            asm("mov.b64 %0, {%1, %1};" : "=l"(a2a[rr]) : "r"(au));
        }

        #pragma unroll
        for (int kk = 0; kk < 8; kk++) {
            const bool even = (kk & 1) == 0;
            unsigned long long* b2c = even ? b2a : b2b;   // current
            unsigned long long* a2c = even ? a2a : a2b;
            unsigned long long* b2n = even ? b2b : b2a;   // next
            unsigned long long* a2n = even ? a2b : a2a;

            // prefetch kk+1 operands BEFORE the FFMA block (>=128 cyc cover)
            if (kk < 7) {
                #pragma unroll
                for (int i = 0; i < 8; i++)
                    b2n[i] = *(const unsigned long long*)(sBc + (kk + 1) * 512 + 2 * l + 64 * i);
                #pragma unroll
                for (int rr = 0; rr < 8; rr++) {
                    unsigned au = __float_as_uint(sA[(kc + kk + 1) * SA_STRIDE + arow + rr]);
                    asm("mov.b64 %0, {%1, %1};" : "=l"(a2n[rr]) : "r"(au));
                }
            }

            // 64 independent FFMA2s (all operands already in registers)
            #pragma unroll
            for (int i = 0; i < 8; i++)
                #pragma unroll
                for (int rr = 0; rr < 8; rr++)
                    asm("fma.rn.f32x2 %0, %1, %2, %0;"
                        : "+l"(acc[rr][i]) : "l"(a2c[rr]), "l"(b2c[i]));
        }
    }

    // ---- xx per row: strictly serial ascending scalar (XLA:CPU schedule) ----
    float xxser = 0.0f;
    if (l < 8) {
        const int row = arow + l;
        float a = 0.0f;
        #pragma unroll 8
        for (int k = 0; k < 512; k++) {
            float v = sA[k * SA_STRIDE + row];
            a = __fadd_rn(a, __fmul_rn(v, v));
        }
        xxser = a;
    }

    // epilogue: dist = (xx - 2*dot) + cc, argmin (min-index ties), ST update
    float warploss = 0.0f;
    #pragma unroll 1
    for (int rr = 0; rr < 8; rr++) {
        const int row = arow + rr;
        const float xx = __shfl_sync(FULLM, xxser, rr);

        float best = 3.4e38f; int bidx = 0;
        #pragma unroll
        for (int i = 0; i < 8; i++) {
            unsigned long long v = acc[rr][i];
            float d0 = __uint_as_float((unsigned)(v & 0xffffffffull));
            float d1 = __uint_as_float((unsigned)(v >> 32));
            int c0 = 2 * l + 64 * i;
            float dist0 = __fadd_rn(__fsub_rn(xx, __fmul_rn(2.0f, d0)), sCc[c0]);
            float dist1 = __fadd_rn(__fsub_rn(xx, __fmul_rn(2.0f, d1)), sCc[c0 + 1]);
            if (dist0 < best) { best = dist0; bidx = c0; }
            if (dist1 < best) { best = dist1; bidx = c0 + 1; }
        }
        #pragma unroll
        for (int o = 16; o; o >>= 1) {
            float ob = __shfl_xor_sync(FULLM, best, o);
            int   oi = __shfl_xor_sync(FULLM, bidx, o);
            if (ob < best || (ob == best && oi < bidx)) { best = ob; bidx = oi; }
        }

        // straight-through residual update replicated op-for-op + commit loss
        const float* crow = cbq + (size_t)bidx * CD;
        float* rrow = g_res + (size_t)(r0 + row) * CD;
        #pragma unroll
        for (int j = 0; j < 16; j++) {
            int k = l + 32 * j;
            float r = sA[k * SA_STRIDE + row];
            float c = crow[k];
            float xst  = __fadd_rn(r, __fsub_rn(c, r));   // xf + (x_d - xf)
            rrow[k]    = __fsub_rn(r, xst);               // residual - quantized
            float diff = __fsub_rn(r, c);                 // xf - x_d
            warploss += diff * diff;                      // scalar; loose tolerance
        }
        if (l == 0) {
            g_code[q * NT + r0 + row] = bidx;
            atomicAdd(&g_hist[q * 512 + bidx], 1.0f);
        }
    }
    #pragma unroll
    for (int o = 16; o; o >>= 1) warploss += __shfl_xor_sync(FULLM, warploss, o);
    if (l == 0) sSt[w] = warploss;
    __syncthreads();
    if (t == 0) {
        float s = 0.0f;
        #pragma unroll
        for (int i = 0; i < 8; i++) s += sSt[i];
        g_losspart[q * 1024 + bid] = s;
    }
}

// ---------------- output: quantized = x - residual_final (transposed) -----
__global__ void write_quant_kernel(const float* __restrict__ x, float* __restrict__ out)
{
    __shared__ float s[32][33];
    int n = blockIdx.z, c0 = blockIdx.y * 32, t0 = blockIdx.x * 32;
    int tx = threadIdx.x, ty = threadIdx.y;
    #pragma unroll
    for (int i = 0; i < 4; i++) {
        int tt = ty + 8 * i;
        s[tt][tx] = g_res[(size_t)(n * TD + t0 + tt) * CD + c0 + tx];
    }
    __syncthreads();
    #pragma unroll
    for (int i = 0; i < 4; i++) {
        int cc = ty + 8 * i;
        size_t o = (size_t)n * CD * TD + (size_t)(c0 + cc) * TD + t0 + tx;
        out[o] = __fsub_rn(x[o], s[tx][cc]);
    }
}

__global__ void write_idx_kernel(float* __restrict__ out, int out_size)
{
    int nt = blockIdx.x * 256 + threadIdx.x;
    if (nt < NT && (size_t)out_size >= OUT_TOTAL) {
        #pragma unroll
        for (int q = 0; q < QL; q++)
            out[IDX_OFF + (size_t)nt * QL + q] = (float)g_code[q * NT + nt];
    }
}

__global__ void finalize_kernel(float* __restrict__ out, int out_size)
{
    __shared__ float red[512];
    const int t = threadIdx.x;
    float tot_loss = 0.0f, tot_perp = 0.0f;
    for (int q = 0; q < QL; q++) {
        red[t] = g_losspart[q * 1024 + t] + g_losspart[q * 1024 + 512 + t];
        __syncthreads();
        for (int st = 256; st > 0; st >>= 1) {
            if (t < st) red[t] += red[t + st];
            __syncthreads();
        }
        tot_loss += red[0];
        __syncthreads();

        float p = g_hist[q * 512 + t] * (1.0f / 65536.0f);
        red[t] = p * logf(p + 1e-7f);
        __syncthreads();
        for (int st = 256; st > 0; st >>= 1) {
            if (t < st) red[t] += red[t + st];
            __syncthreads();
        }
        tot_perp += expf(-red[0]);
        __syncthreads();
    }
    if (t == 0 && (size_t)out_size >= OUT_TOTAL) {
        out[LOSS_OFF]     = tot_loss * (1.0f / ((float)NT * (float)CD)) / (float)QL;
        out[LOSS_OFF + 1] = tot_perp / (float)QL;
    }
}

// ---------------- launch --------------------------------------------------
extern "C" void kernel_launch(void* const* d_in, const int* in_sizes, int n_in,
                              void* d_out, int out_size)
{
    const float* x  = (const float*)d_in[0];
    const float* cb = (const float*)d_in[1];
    if (n_in >= 2 && in_sizes[0] < in_sizes[1]) {
        const float* tmp = x; x = cb; cb = tmp;
    }
    float* out = (float*)d_out;

    cudaFuncSetAttribute(vq_layer_kernel,
                         cudaFuncAttributeMaxDynamicSharedMemorySize, SMEM_BYTES);

    prep_kernel<<<12, 256>>>(cb);
    transpose_cb_kernel<<<dim3(KCODE / 32, CD / 32, QL), dim3(32, 8)>>>(cb);
    transpose_in_kernel<<<dim3(TD / 32, CD / 32, NB), dim3(32, 8)>>>(x);
    for (int q = 0; q < QL; q++)
        vq_layer_kernel<<<NT / 64, 256, SMEM_BYTES>>>(cb, q);
    write_quant_kernel<<<dim3(TD / 32, CD / 32, NB), dim3(32, 8)>>>(x, out);
    write_idx_kernel<<<NT / 256, 256>>>(out, out_size);
    finalize_kernel<<<1, 512>>>(out, out_size);
}

// round 17
// speedup vs baseline: 1.1920x; 1.0660x over previous
#include <cuda_runtime.h>
#include <math.h>
#include <stdint.h>

#define NB   32
#define CD   512
#define TD   2048
#define NT   (NB * TD)        // 65536
#define KCODE 512
#define QL   6
#define NCT  (NB * CD * TD)   // 33554432

#define IDX_OFF   ((size_t)NCT)
#define LOSS_OFF  (IDX_OFF + (size_t)NT * QL)   // 33947648
#define OUT_TOTAL (LOSS_OFF + 2)                 // 33947650

#define FULLM 0xffffffffu

// ---------------- device scratch (static globals; no runtime alloc) -------
__device__ float g_res[(size_t)NT * CD];   // residual state, row-major [(n,t), c]
__device__ float g_cbT[QL * KCODE * CD];   // codebook transposed: [q][k][code]
__device__ float g_cc[QL * KCODE];         // ||c||^2, serial ascending schedule
__device__ int   g_code[QL * NT];
__device__ float g_hist[QL * KCODE];
__device__ float g_losspart[QL * 1024];

// ---------------- prep: zero hist + code norms ----------------------------
// XLA:CPU non-vectorized reduce: strictly serial ascending, separate mul/add.
__global__ void prep_kernel(const float* __restrict__ cb)
{
    int gid = blockIdx.x * 256 + threadIdx.x;
    if (gid < QL * KCODE) {
        g_hist[gid] = 0.0f;
        const float* row = cb + (size_t)gid * CD;
        float a = 0.0f;
        #pragma unroll 8
        for (int k = 0; k < CD; k++) {
            float v = row[k];
            a = __fadd_rn(a, __fmul_rn(v, v));
        }
        g_cc[gid] = a;
    }
}

// ---------------- transpose codebook: [q][code][k] -> [q][k][code] --------
__global__ void transpose_cb_kernel(const float* __restrict__ cb)
{
    __shared__ float s[32][33];
    int qq = blockIdx.z, c0 = blockIdx.x * 32, k0 = blockIdx.y * 32;
    int tx = threadIdx.x, ty = threadIdx.y;
    const float* src = cb + (size_t)qq * KCODE * CD;
    float* dst = g_cbT + (size_t)qq * KCODE * CD;
    #pragma unroll
    for (int i = 0; i < 4; i++) {
        int cc = ty + 8 * i;
        s[cc][tx] = src[(size_t)(c0 + cc) * CD + k0 + tx];
    }
    __syncthreads();
    #pragma unroll
    for (int i = 0; i < 4; i++) {
        int kk = ty + 8 * i;
        dst[(size_t)(k0 + kk) * KCODE + c0 + tx] = s[tx][kk];
    }
}

// ---------------- transpose x [N,C,T] -> residual [(n,t), c] --------------
__global__ void transpose_in_kernel(const float* __restrict__ x)
{
    __shared__ float s[32][33];
    int n = blockIdx.z, c0 = blockIdx.y * 32, t0 = blockIdx.x * 32;
    int tx = threadIdx.x, ty = threadIdx.y;
    #pragma unroll
    for (int i = 0; i < 4; i++) {
        int cc = ty + 8 * i;
        s[cc][tx] = x[(size_t)n * CD * TD + (size_t)(c0 + cc) * TD + t0 + tx];
    }
    __syncthreads();
    #pragma unroll
    for (int i = 0; i < 4; i++) {
        int tt = ty + 8 * i;
        g_res[(size_t)(n * TD + t0 + tt) * CD + c0 + tx] = s[tx][tt];
    }
}

// ---------------- mbarrier / bulk-copy helpers ----------------------------
__device__ __forceinline__ void mbar_init(uint32_t mbar) {
    asm volatile("mbarrier.init.shared.b64 [%0], %1;" :: "r"(mbar), "r"(1u) : "memory");
}
__device__ __forceinline__ void mbar_expect_tx(uint32_t mbar, uint32_t bytes) {
    asm volatile("mbarrier.arrive.expect_tx.shared.b64 _, [%0], %1;"
                 :: "r"(mbar), "r"(bytes) : "memory");
}
__device__ __forceinline__ void bulk_g2s(uint32_t dst, const void* src, uint32_t bytes, uint32_t mbar) {
    asm volatile("cp.async.bulk.shared::cta.global.mbarrier::complete_tx::bytes [%0], [%1], %2, [%3];"
                 :: "r"(dst), "l"(src), "r"(bytes), "r"(mbar) : "memory");
}
__device__ __forceinline__ void mbar_wait(uint32_t mbar, uint32_t phase) {
    asm volatile(
        "{\n\t.reg .pred P;\n\t"
        "W_%=:\n\t"
        "mbarrier.try_wait.parity.acquire.cta.shared::cta.b64 P, [%0], %1, 0x989680;\n\t"
        "@P bra D_%=;\n\t"
        "bra W_%=;\n\t"
        "D_%=:\n\t}"
        :: "r"(mbar), "r"(phase) : "memory");
}

// ---------------- fused VQ layer: scores + argmin + update ----------------
// 256 threads, 64 rows x 512 codes per block; warp w owns rows 8w..8w+7.
// Lane l owns codes {4l..4l+3} + 128*i (i=0..3): 4x LDS.128 per kk for B,
// 4x LDS.64 broadcast per kk for A. B staged via ONE cp.async.bulk per
// chunk (4-stage mbarrier ring) -- near-zero staging instruction cost.
#define SA_STRIDE 66
#define SA_WORDS  (512 * SA_STRIDE)      // 33792 floats
#define SB_STAGE  (8 * 512)              // 4096 floats per stage (16 KB)
#define NSTAGE    4
#define MBAR_OFF  (SA_WORDS + NSTAGE * SB_STAGE + 512 + 16)   // even float idx
#define SMEM_FLOATS (MBAR_OFF + 16)
#define SMEM_BYTES (SMEM_FLOATS * 4)

__global__ __launch_bounds__(256, 1) void vq_layer_kernel(const float* __restrict__ cb_all, int q)
{
    extern __shared__ float sm[];
    float* sA  = sm;
    float* sB  = sm + SA_WORDS;
    float* sCc = sm + SA_WORDS + NSTAGE * SB_STAGE;
    float* sSt = sCc + 512;

    const float* cbq  = cb_all + (size_t)q * KCODE * CD;   // row-major (epilogue)
    const float* cbTq = g_cbT + (size_t)q * KCODE * CD;    // [k][code] (mainloop)
    const int t = threadIdx.x;
    const int bid = blockIdx.x;
    const int r0 = bid * 64;

    const uint32_t smem_u32 = (uint32_t)__cvta_generic_to_shared(sm);
    const uint32_t sB_u32   = smem_u32 + SA_WORDS * 4;
    const uint32_t mbar_u32 = smem_u32 + MBAR_OFF * 4;

    for (int i = t; i < 512; i += 256) sCc[i] = g_cc[q * 512 + i];

    // init mbarriers, then prologue: bulk-copy stages 0..2
    if (t == 0) {
        #pragma unroll
        for (int b = 0; b < NSTAGE; b++) mbar_init(mbar_u32 + b * 8);
    }
    __syncthreads();
    if (t == 0) {
        #pragma unroll
        for (int s = 0; s < 3; s++) {
            mbar_expect_tx(mbar_u32 + s * 8, SB_STAGE * 4);
            bulk_g2s(sB_u32 + s * SB_STAGE * 4, cbTq + (size_t)s * SB_STAGE,
                     SB_STAGE * 4, mbar_u32 + s * 8);
        }
    }

    // stage A (64 rows x 512) into [k][row] layout (overlaps bulk copies)
    const float* resblk = g_res + (size_t)r0 * CD;
    #pragma unroll 4
    for (int j = 0; j < 128; j++) {
        int e = t + 256 * j;
        int row = e >> 9;
        int k = e & 511;
        sA[k * SA_STRIDE + row] = resblk[e];
    }

    unsigned long long acc[8][8];
    #pragma unroll
    for (int rr = 0; rr < 8; rr++)
        #pragma unroll
        for (int i = 0; i < 8; i++) acc[rr][i] = 0ull;

    const int w = t >> 5, l = t & 31;
    const int arow = 8 * w;

    // k strictly ascending, single fp32 accumulator per output, FMA
    // (bit-identical chains to the passing R8/R13/R15 kernels)
    #pragma unroll 1
    for (int s = 0; s < 64; s++) {
        const int kc = 8 * s;
        __syncthreads();     // all reads of buffer (s-1)&3 finished (and A staged)

        // issue stage s+3 into buffer (s+3)&3 == (s-1)&3 (just drained)
        if (t == 0 && s + 3 < 64) {
            const int st = s + 3;
            mbar_expect_tx(mbar_u32 + (st & 3) * 8, SB_STAGE * 4);
            bulk_g2s(sB_u32 + (st & 3) * SB_STAGE * 4, cbTq + (size_t)st * SB_STAGE,
                     SB_STAGE * 4, mbar_u32 + (st & 3) * 8);
        }

        // wait for stage s data
        mbar_wait(mbar_u32 + (s & 3) * 8, (s >> 2) & 1);

        const float* sBc = sB + (s & 3) * SB_STAGE;
        #pragma unroll
        for (int kk = 0; kk < 8; kk++) {
            unsigned long long b2[8];
            #pragma unroll
            for (int i = 0; i < 4; i++) {
                ulonglong2 v = *(const ulonglong2*)(sBc + kk * 512 + 4 * l + 128 * i);
                b2[2 * i]     = v.x;    // codes 4l+128i, 4l+128i+1
                b2[2 * i + 1] = v.y;    // codes 4l+128i+2, 4l+128i+3
            }
            unsigned long long a2[8];
            #pragma unroll
            for (int rp = 0; rp < 4; rp++) {
                float2 ap = *(const float2*)(sA + (kc + kk) * SA_STRIDE + arow + 2 * rp);
                unsigned ax = __float_as_uint(ap.x), ay = __float_as_uint(ap.y);
                asm("mov.b64 %0, {%1, %1};" : "=l"(a2[2 * rp])     : "r"(ax));
                asm("mov.b64 %0, {%1, %1};" : "=l"(a2[2 * rp + 1]) : "r"(ay));
            }
            #pragma unroll
            for (int i = 0; i < 8; i++)
                #pragma unroll
                for (int rr = 0; rr < 8; rr++)
                    asm("fma.rn.f32x2 %0, %1, %2, %0;"
                        : "+l"(acc[rr][i]) : "l"(a2[rr]), "l"(b2[i]));
        }
    }

    // ---- xx per row: strictly serial ascending scalar (XLA:CPU schedule) ----
    float xxser = 0.0f;
    if (l < 8) {
        const int row = arow + l;
        float a = 0.0f;
        #pragma unroll 8
        for (int k = 0; k < 512; k++) {
            float v = sA[k * SA_STRIDE + row];
            a = __fadd_rn(a, __fmul_rn(v, v));
        }
        xxser = a;
    }

    // epilogue: dist = (xx - 2*dot) + cc, argmin (min-index ties), ST update
    float warploss = 0.0f;
    #pragma unroll 1
    for (int rr = 0; rr < 8; rr++) {
        const int row = arow + rr;
        const float xx = __shfl_sync(FULLM, xxser, rr);

        float best = 3.4e38f; int bidx = 0;
        #pragma unroll
        for (int i = 0; i < 8; i++) {
            unsigned long long v = acc[rr][i];
            float d0 = __uint_as_float((unsigned)(v & 0xffffffffull));
            float d1 = __uint_as_float((unsigned)(v >> 32));
            int c0 = 4 * l + 128 * (i >> 1) + 2 * (i & 1);   // ascending in i
            float dist0 = __fadd_rn(__fsub_rn(xx, __fmul_rn(2.0f, d0)), sCc[c0]);
            float dist1 = __fadd_rn(__fsub_rn(xx, __fmul_rn(2.0f, d1)), sCc[c0 + 1]);
            if (dist0 < best) { best = dist0; bidx = c0; }
            if (dist1 < best) { best = dist1; bidx = c0 + 1; }
        }
        #pragma unroll
        for (int o = 16; o; o >>= 1) {
            float ob = __shfl_xor_sync(FULLM, best, o);
            int   oi = __shfl_xor_sync(FULLM, bidx, o);
            if (ob < best || (ob == best && oi < bidx)) { best = ob; bidx = oi; }
        }

        // straight-through residual update replicated op-for-op + commit loss
        const float* crow = cbq + (size_t)bidx * CD;
        float* rrow = g_res + (size_t)(r0 + row) * CD;
        #pragma unroll
        for (int j = 0; j < 16; j++) {
            int k = l + 32 * j;
            float r = sA[k * SA_STRIDE + row];
            float c = crow[k];
            float xst  = __fadd_rn(r, __fsub_rn(c, r));   // xf + (x_d - xf)
            rrow[k]    = __fsub_rn(r, xst);               // residual - quantized
            float diff = __fsub_rn(r, c);                 // xf - x_d
            warploss += diff * diff;                      // scalar; loose tolerance
        }
        if (l == 0) {
            g_code[q * NT + r0 + row] = bidx;
            atomicAdd(&g_hist[q * 512 + bidx], 1.0f);
        }
    }
    #pragma unroll
    for (int o = 16; o; o >>= 1) warploss += __shfl_xor_sync(FULLM, warploss, o);
    if (l == 0) sSt[w] = warploss;
    __syncthreads();
    if (t == 0) {
        float s = 0.0f;
        #pragma unroll
        for (int i = 0; i < 8; i++) s += sSt[i];
        g_losspart[q * 1024 + bid] = s;
    }
}

// ---------------- output: quantized = x - residual_final (transposed) -----
__global__ void write_quant_kernel(const float* __restrict__ x, float* __restrict__ out)
{
    __shared__ float s[32][33];
    int n = blockIdx.z, c0 = blockIdx.y * 32, t0 = blockIdx.x * 32;
    int tx = threadIdx.x, ty = threadIdx.y;
    #pragma unroll
    for (int i = 0; i < 4; i++) {
        int tt = ty + 8 * i;
        s[tt][tx] = g_res[(size_t)(n * TD + t0 + tt) * CD + c0 + tx];
    }
    __syncthreads();
    #pragma unroll
    for (int i = 0; i < 4; i++) {
        int cc = ty + 8 * i;
        size_t o = (size_t)n * CD * TD + (size_t)(c0 + cc) * TD + t0 + tx;
        out[o] = __fsub_rn(x[o], s[tx][cc]);
    }
}

__global__ void write_idx_kernel(float* __restrict__ out, int out_size)
{
    int nt = blockIdx.x * 256 + threadIdx.x;
    if (nt < NT && (size_t)out_size >= OUT_TOTAL) {
        #pragma unroll
        for (int q = 0; q < QL; q++)
            out[IDX_OFF + (size_t)nt * QL + q] = (float)g_code[q * NT + nt];
    }
}

__global__ void finalize_kernel(float* __restrict__ out, int out_size)
{
    __shared__ float red[512];
    const int t = threadIdx.x;
    float tot_loss = 0.0f, tot_perp = 0.0f;
    for (int q = 0; q < QL; q++) {
        red[t] = g_losspart[q * 1024 + t] + g_losspart[q * 1024 + 512 + t];
        __syncthreads();
        for (int st = 256; st > 0; st >>= 1) {
            if (t < st) red[t] += red[t + st];
            __syncthreads();
        }
        tot_loss += red[0];
        __syncthreads();

        float p = g_hist[q * 512 + t] * (1.0f / 65536.0f);
        red[t] = p * logf(p + 1e-7f);
        __syncthreads();
        for (int st = 256; st > 0; st >>= 1) {
            if (t < st) red[t] += red[t + st];
            __syncthreads();
        }
        tot_perp += expf(-red[0]);
        __syncthreads();
    }
    if (t == 0 && (size_t)out_size >= OUT_TOTAL) {
        out[LOSS_OFF]     = tot_loss * (1.0f / ((float)NT * (float)CD)) / (float)QL;
        out[LOSS_OFF + 1] = tot_perp / (float)QL;
    }
}

// ---------------- launch --------------------------------------------------
extern "C" void kernel_launch(void* const* d_in, const int* in_sizes, int n_in,
                              void* d_out, int out_size)
{
    const float* x  = (const float*)d_in[0];
    const float* cb = (const float*)d_in[1];
    if (n_in >= 2 && in_sizes[0] < in_sizes[1]) {
        const float* tmp = x; x = cb; cb = tmp;
    }
    float* out = (float*)d_out;

    cudaFuncSetAttribute(vq_layer_kernel,
                         cudaFuncAttributeMaxDynamicSharedMemorySize, SMEM_BYTES);

    prep_kernel<<<12, 256>>>(cb);
    transpose_cb_kernel<<<dim3(KCODE / 32, CD / 32, QL), dim3(32, 8)>>>(cb);
    transpose_in_kernel<<<dim3(TD / 32, CD / 32, NB), dim3(32, 8)>>>(x);
    for (int q = 0; q < QL; q++)
        vq_layer_kernel<<<NT / 64, 256, SMEM_BYTES>>>(cb, q);
    write_quant_kernel<<<dim3(TD / 32, CD / 32, NB), dim3(32, 8)>>>(x, out);
    write_idx_kernel<<<NT / 256, 256>>>(out, out_size);
    finalize_kernel<<<1, 512>>>(out, out_size);
}